// round 14
// baseline (speedup 1.0000x reference)
#include <cuda_runtime.h>
#include <cuda_bf16.h>
#include <cstdint>

// Problem constants (from reference)
#define NPAT 50000
#define NAUT 100000
#define HF   128

// ---------------- scratch (device globals; no allocation allowed) ----------
__device__ float g_aggA[(size_t)NPAT * HF];  // cites -> patent aggregation
__device__ float g_aggB[(size_t)NPAT * HF];  // ao    -> patent aggregation
__device__ float g_aggH[(size_t)NAUT * HF];  // ha    -> author aggregation
__device__ float g_p1[(size_t)NPAT * HF];
__device__ float g_a1[(size_t)NAUT * HF];
__device__ float g_p2[(size_t)NPAT * HF];
__device__ float g_cA[NPAT];   // becomes 1/max(cnt,1) after inv kernel
__device__ float g_cB[NPAT];
__device__ float g_cH[NAUT];

// ---------------- degree count: all 3 relations in one launch ---------------
__global__ __launch_bounds__(256) void degree3_kernel(
        const int* __restrict__ dA,
        const int* __restrict__ dB,
        const int* __restrict__ dH,
        float* __restrict__ cA,
        float* __restrict__ cB,
        float* __restrict__ cH, int E) {
    int i = blockIdx.x * blockDim.x + threadIdx.x;
    if (i < E) {
        asm volatile("red.global.add.f32 [%0], %1;"
                     :: "l"(cA + __ldg(dA + i)), "f"(1.0f) : "memory");
        asm volatile("red.global.add.f32 [%0], %1;"
                     :: "l"(cB + __ldg(dB + i)), "f"(1.0f) : "memory");
        asm volatile("red.global.add.f32 [%0], %1;"
                     :: "l"(cH + __ldg(dH + i)), "f"(1.0f) : "memory");
    }
}

// ---------------- scatter: one warp per edge, vector red --------------------
__global__ __launch_bounds__(256) void scatter_kernel(
        const float* __restrict__ x,
        const int* __restrict__ src,
        const int* __restrict__ dst,
        float* __restrict__ agg,
        int E) {
    int warp = (blockIdx.x * blockDim.x + threadIdx.x) >> 5;
    int lane = threadIdx.x & 31;
    if (warp >= E) return;
    int s = __ldg(src + warp);
    int d = __ldg(dst + warp);
    float4 v = __ldg((const float4*)(x + (size_t)s * HF) + lane);
    float* ag = agg + (size_t)d * HF + lane * 4;
    asm volatile("red.global.add.v4.f32 [%0], {%1, %2, %3, %4};"
                 :: "l"(ag), "f"(v.x), "f"(v.y), "f"(v.z), "f"(v.w)
                 : "memory");
}

// ---------------- cnt -> 1/max(cnt,1), all three arrays in one launch -------
__global__ __launch_bounds__(256) void inv3_kernel(
        float* __restrict__ cA, float* __restrict__ cB,
        float* __restrict__ cH) {
    int i = blockIdx.x * blockDim.x + threadIdx.x;
    if (i < NPAT) {
        cA[i] = 1.0f / fmaxf(cA[i], 1.0f);
        cB[i] = 1.0f / fmaxf(cB[i], 1.0f);
    }
    if (i < NAUT) cH[i] = 1.0f / fmaxf(cH[i], 1.0f);
}

// ---------------- fused SAGE GEMM -------------------------------------------
// C[M,128] = relu( alpha * ( A0*inv0 @ W0^T + A1*inv1 @ W1^T
//                          + A2 @ (W2a + W2b)^T + b0 + b1 ) )
// All W row-major [128 out][128 in];  A row-major [M][128].
//
// Thread (tx,ty), tx=tid&15, ty=tid>>4:
//   rows  = ty*8 + {0..7}
//   cols  = {4tx..4tx+3} U {64+4tx..64+4tx+3}   (conflict-free LDS.128 pattern)
#define BM 128
#define BN 128
#define BK 32
#define SROW 132               // smem row stride in floats (33 float4, 16B aligned)
#define SROW4 33               // in float4 units

// Per-thread global fetch of one (A,W) k-slab into registers.
// Each thread covers row `ml`, k-range [kt+k0, kt+k0+16).
__device__ __forceinline__ void fetch_tiles(
    const float* __restrict__ A, const float* __restrict__ Wp,
    const float* __restrict__ Wq,
    int gm, int M, int ml, int kt, int k0,
    float4 aP[4], float4 wP[4])
{
    const float* arow = A + (size_t)gm * HF + kt + k0;
    const float* wrow = Wp + (size_t)ml * HF + kt + k0;
#pragma unroll
    for (int j = 0; j < 4; j++) {
        aP[j] = (gm < M) ? __ldg((const float4*)(arow) + j)
                         : make_float4(0.f, 0.f, 0.f, 0.f);
        float4 w = __ldg((const float4*)(wrow) + j);
        if (Wq) {
            float4 w2 = __ldg((const float4*)(Wq + (size_t)ml * HF + kt + k0) + j);
            w.x += w2.x; w.y += w2.y; w.z += w2.z; w.w += w2.w;
        }
        wP[j] = w;
    }
}

__global__ __launch_bounds__(256) void sage_gemm(
    const float* __restrict__ A0, const float* __restrict__ inv0, const float* __restrict__ W0,
    const float* __restrict__ A1, const float* __restrict__ inv1, const float* __restrict__ W1,
    const float* __restrict__ A2, const float* __restrict__ W2a, const float* __restrict__ W2b,
    const float* __restrict__ b0, const float* __restrict__ b1,
    float alpha, int M, float* __restrict__ C)
{
    __shared__ __align__(16) float As[BK * SROW];    // As[k][m]
    __shared__ __align__(16) float Ws[BK * SROW];    // Ws[k][n]

    const int tid = threadIdx.x;
    const int tx = tid & 15;
    const int ty = tid >> 4;
    const int bm = blockIdx.x * BM;

    float acc[8][8];                   // [row r][col c]; c<4 -> 4tx+c, c>=4 -> 64+4tx+c-4
#pragma unroll
    for (int r = 0; r < 8; r++)
#pragma unroll
        for (int c = 0; c < 8; c++) acc[r][c] = 0.f;

    const int ml = tid >> 1;              // 0..127 row within tile
    const int k0 = (tid & 1) * 16;        // 0 or 16
    const int gm = bm + ml;

    const float4* As4 = (const float4*)As;
    const float4* Ws4 = (const float4*)Ws;

#pragma unroll 1
    for (int s = 0; s < 3; ++s) {
        const float* A = (s == 0) ? A0 : (s == 1) ? A1 : A2;
        if (A == nullptr) continue;
        const float* Wp = (s == 0) ? W0 : (s == 1) ? W1 : W2a;
        const float* Wq = (s == 2) ? W2b : nullptr;
        const float* invp = (s == 0) ? inv0 : (s == 1) ? inv1 : nullptr;

        float sc = 0.f;
        if (gm < M) sc = invp ? __ldg(invp + gm) : 1.0f;

        // software pipeline: prefetch k-tile 0 into registers
        float4 aP[4], wP[4];
        fetch_tiles(A, Wp, Wq, gm, M, ml, 0, k0, aP, wP);

#pragma unroll 1
        for (int kt = 0; kt < HF; kt += BK) {
            // ---- store the prefetched slab to smem (transposed: [k][row]) ----
#pragma unroll
            for (int j = 0; j < 4; j++) {
                int kb = k0 + j * 4;
                As[(kb + 0) * SROW + ml] = aP[j].x * sc;
                As[(kb + 1) * SROW + ml] = aP[j].y * sc;
                As[(kb + 2) * SROW + ml] = aP[j].z * sc;
                As[(kb + 3) * SROW + ml] = aP[j].w * sc;
                Ws[(kb + 0) * SROW + ml] = wP[j].x;
                Ws[(kb + 1) * SROW + ml] = wP[j].y;
                Ws[(kb + 2) * SROW + ml] = wP[j].z;
                Ws[(kb + 3) * SROW + ml] = wP[j].w;
            }
            __syncthreads();

            // ---- prefetch next slab (overlaps with compute below) ----
            if (kt + BK < HF)
                fetch_tiles(A, Wp, Wq, gm, M, ml, kt + BK, k0, aP, wP);

            // ---- compute: conflict-free LDS.128 reads ----
#pragma unroll
            for (int kk = 0; kk < BK; ++kk) {
                float4 av0 = As4[kk * SROW4 + ty * 2];       // rows 8ty..8ty+3
                float4 av1 = As4[kk * SROW4 + ty * 2 + 1];   // rows 8ty+4..8ty+7
                float4 bv0 = Ws4[kk * SROW4 + tx];           // cols 4tx..4tx+3
                float4 bv1 = Ws4[kk * SROW4 + 16 + tx];      // cols 64+4tx..+3
                float a[8] = {av0.x, av0.y, av0.z, av0.w,
                              av1.x, av1.y, av1.z, av1.w};
                float b[8] = {bv0.x, bv0.y, bv0.z, bv0.w,
                              bv1.x, bv1.y, bv1.z, bv1.w};
#pragma unroll
                for (int r = 0; r < 8; r++)
#pragma unroll
                    for (int c = 0; c < 8; c++) acc[r][c] += a[r] * b[c];
            }
            __syncthreads();
        }
    }

    // epilogue: bias, alpha, relu; cols are {4tx..4tx+3} and {64+4tx..64+4tx+3}
    float bias[8];
#pragma unroll
    for (int c = 0; c < 8; c++) {
        int n = (c < 4) ? (tx * 4 + c) : (64 + tx * 4 + (c - 4));
        float bv = b0 ? __ldg(b0 + n) : 0.f;
        if (b1) bv += __ldg(b1 + n);
        bias[c] = bv;
    }
#pragma unroll
    for (int r = 0; r < 8; r++) {
        int gmr = bm + ty * 8 + r;
        if (gmr >= M) continue;
        float* crow = C + (size_t)gmr * HF;
        float4 lo, hi;
        lo.x = fmaxf(alpha * (acc[r][0] + bias[0]), 0.f);
        lo.y = fmaxf(alpha * (acc[r][1] + bias[1]), 0.f);
        lo.z = fmaxf(alpha * (acc[r][2] + bias[2]), 0.f);
        lo.w = fmaxf(alpha * (acc[r][3] + bias[3]), 0.f);
        hi.x = fmaxf(alpha * (acc[r][4] + bias[4]), 0.f);
        hi.y = fmaxf(alpha * (acc[r][5] + bias[5]), 0.f);
        hi.z = fmaxf(alpha * (acc[r][6] + bias[6]), 0.f);
        hi.w = fmaxf(alpha * (acc[r][7] + bias[7]), 0.f);
        ((float4*)(crow))[tx] = lo;
        ((float4*)(crow + 64))[tx] = hi;
    }
}

// ---------------- final head: out[M,8] = p2 @ linW^T + lin_b ----------------
__global__ __launch_bounds__(256) void head_kernel(
        const float* __restrict__ p2,
        const float* __restrict__ W,   // [8,128]
        const float* __restrict__ b,   // [8]
        float* __restrict__ out, int M) {
    int warp = (blockIdx.x * blockDim.x + threadIdx.x) >> 5;
    int lane = threadIdx.x & 31;
    if (warp >= M) return;
    const float* row = p2 + (size_t)warp * HF;
    float v0 = row[lane], v1 = row[lane + 32], v2 = row[lane + 64], v3 = row[lane + 96];
#pragma unroll
    for (int c = 0; c < 8; c++) {
        const float* w = W + c * HF;
        float p = v0 * __ldg(w + lane) + v1 * __ldg(w + lane + 32)
                + v2 * __ldg(w + lane + 64) + v3 * __ldg(w + lane + 96);
#pragma unroll
        for (int o = 16; o; o >>= 1) p += __shfl_xor_sync(0xffffffffu, p, o);
        if (lane == 0) out[(size_t)warp * 8 + c] = p + __ldg(b + c);
    }
}

// ---------------- host orchestration ----------------------------------------
extern "C" void kernel_launch(void* const* d_in, const int* in_sizes, int n_in,
                              void* d_out, int out_size) {
    const float* x_p   = (const float*)d_in[0];
    const float* x_a   = (const float*)d_in[1];
    const int* cites_s = (const int*)d_in[2];
    const int* cites_d = (const int*)d_in[3];
    const int* ao_s    = (const int*)d_in[4];
    const int* ao_d    = (const int*)d_in[5];
    const int* ha_s    = (const int*)d_in[6];
    const int* ha_d    = (const int*)d_in[7];
    const float* l1c_Wl = (const float*)d_in[8];
    const float* l1c_bl = (const float*)d_in[9];
    const float* l1c_Wr = (const float*)d_in[10];
    const float* l1a_Wl = (const float*)d_in[11];
    const float* l1a_bl = (const float*)d_in[12];
    const float* l1a_Wr = (const float*)d_in[13];
    const float* l1h_Wl = (const float*)d_in[14];
    const float* l1h_bl = (const float*)d_in[15];
    const float* l1h_Wr = (const float*)d_in[16];
    const float* l2c_Wl = (const float*)d_in[17];
    const float* l2c_bl = (const float*)d_in[18];
    const float* l2c_Wr = (const float*)d_in[19];
    const float* l2a_Wl = (const float*)d_in[20];
    const float* l2a_bl = (const float*)d_in[21];
    const float* l2a_Wr = (const float*)d_in[22];
    // l2h_* (indices 23..25) are dead code in the reference
    const float* lin_W  = (const float*)d_in[26];
    const float* lin_b  = (const float*)d_in[27];
    float* out = (float*)d_out;

    const int E = in_sizes[2];

    float *aggA, *aggB, *aggH, *p1, *a1, *p2, *cA, *cB, *cH;
    cudaGetSymbolAddress((void**)&aggA, g_aggA);
    cudaGetSymbolAddress((void**)&aggB, g_aggB);
    cudaGetSymbolAddress((void**)&aggH, g_aggH);
    cudaGetSymbolAddress((void**)&p1, g_p1);
    cudaGetSymbolAddress((void**)&a1, g_a1);
    cudaGetSymbolAddress((void**)&p2, g_p2);
    cudaGetSymbolAddress((void**)&cA, g_cA);
    cudaGetSymbolAddress((void**)&cB, g_cB);
    cudaGetSymbolAddress((void**)&cH, g_cH);

    // zero layer-1 aggregation buffers + counts (graph-capturable memset nodes)
    cudaMemsetAsync(aggA, 0, (size_t)NPAT * HF * sizeof(float));
    cudaMemsetAsync(aggB, 0, (size_t)NPAT * HF * sizeof(float));
    cudaMemsetAsync(aggH, 0, (size_t)NAUT * HF * sizeof(float));
    cudaMemsetAsync(cA, 0, NPAT * sizeof(float));
    cudaMemsetAsync(cB, 0, NPAT * sizeof(float));
    cudaMemsetAsync(cH, 0, NAUT * sizeof(float));

    const int SCAT_B = (E * 32 + 255) / 256;
    const int DEG_B = (E + 255) / 256;
    // layer-1 scatters (feature sum) + degree counts.
    // The two x_p-reading scatters run back-to-back for L2 reuse of x_p rows.
    scatter_kernel<<<SCAT_B, 256>>>(x_p, cites_s, cites_d, aggA, E);
    scatter_kernel<<<SCAT_B, 256>>>(x_p, ha_s, ha_d, aggH, E);
    scatter_kernel<<<SCAT_B, 256>>>(x_a, ao_s, ao_d, aggB, E);
    degree3_kernel<<<DEG_B, 256>>>(cites_d, ao_d, ha_d, cA, cB, cH, E);

    inv3_kernel<<<(NAUT + 255) / 256, 256>>>(cA, cB, cH);

    const int GP = (NPAT + BM - 1) / BM;   // 391
    const int GA = (NAUT + BM - 1) / BM;   // 782

    // p1 = relu(0.5*(meanA@Wlc^T + meanB@Wla^T + x_p@(Wrc+Wra)^T + blc + bla))
    sage_gemm<<<GP, 256>>>(aggA, cA, l1c_Wl,
                           aggB, cB, l1a_Wl,
                           x_p, l1c_Wr, l1a_Wr,
                           l1c_bl, l1a_bl,
                           0.5f, NPAT, p1);
    // a1 = relu(meanH@Wlh^T + x_a@Wrh^T + blh)
    sage_gemm<<<GA, 256>>>(aggH, cH, l1h_Wl,
                           nullptr, nullptr, nullptr,
                           x_a, l1h_Wr, nullptr,
                           l1h_bl, nullptr,
                           1.0f, NAUT, a1);

    // layer-2 aggregations (same edges => same counts; cA/cB already hold inverses)
    cudaMemsetAsync(aggA, 0, (size_t)NPAT * HF * sizeof(float));
    cudaMemsetAsync(aggB, 0, (size_t)NPAT * HF * sizeof(float));
    scatter_kernel<<<SCAT_B, 256>>>(p1, cites_s, cites_d, aggA, E);
    scatter_kernel<<<SCAT_B, 256>>>(a1, ao_s, ao_d, aggB, E);

    // p2 = relu(0.5*(meanA@Wlc2^T + meanB@Wla2^T + p1@(Wrc2+Wra2)^T + blc2 + bla2))
    sage_gemm<<<GP, 256>>>(aggA, cA, l2c_Wl,
                           aggB, cB, l2a_Wl,
                           p1, l2c_Wr, l2a_Wr,
                           l2c_bl, l2a_bl,
                           0.5f, NPAT, p2);

    // out = p2 @ lin_W^T + lin_b
    head_kernel<<<(NPAT * 32 + 255) / 256, 256>>>(p2, lin_W, lin_b, out, NPAT);
}

// round 17
// speedup vs baseline: 1.3664x; 1.3664x over previous
#include <cuda_runtime.h>
#include <cuda_bf16.h>
#include <cstdint>

// Problem constants (from reference)
#define NPAT 50000
#define NAUT 100000
#define HF   128

// ---------------- scratch (device globals; no allocation allowed) ----------
__device__ float g_aggA[(size_t)NPAT * HF];  // cites -> patent aggregation
__device__ float g_aggB[(size_t)NPAT * HF];  // ao    -> patent aggregation
__device__ float g_aggH[(size_t)NAUT * HF];  // ha    -> author aggregation
__device__ float g_p1[(size_t)NPAT * HF];
__device__ float g_a1[(size_t)NAUT * HF];
__device__ float g_p2[(size_t)NPAT * HF];
__device__ float g_cA[NPAT];   // becomes 1/max(cnt,1) after inv kernel
__device__ float g_cB[NPAT];
__device__ float g_cH[NAUT];

// ---------------- degree count: all 3 relations in one launch ---------------
__global__ __launch_bounds__(256) void degree3_kernel(
        const int* __restrict__ dA,
        const int* __restrict__ dB,
        const int* __restrict__ dH,
        float* __restrict__ cA,
        float* __restrict__ cB,
        float* __restrict__ cH, int E) {
    int i = blockIdx.x * blockDim.x + threadIdx.x;
    if (i < E) {
        asm volatile("red.global.add.f32 [%0], %1;"
                     :: "l"(cA + __ldg(dA + i)), "f"(1.0f) : "memory");
        asm volatile("red.global.add.f32 [%0], %1;"
                     :: "l"(cB + __ldg(dB + i)), "f"(1.0f) : "memory");
        asm volatile("red.global.add.f32 [%0], %1;"
                     :: "l"(cH + __ldg(dH + i)), "f"(1.0f) : "memory");
    }
}

// ---------------- scatter: one warp per edge, vector red --------------------
__global__ __launch_bounds__(256) void scatter_kernel(
        const float* __restrict__ x,
        const int* __restrict__ src,
        const int* __restrict__ dst,
        float* __restrict__ agg,
        int E) {
    int warp = (blockIdx.x * blockDim.x + threadIdx.x) >> 5;
    int lane = threadIdx.x & 31;
    if (warp >= E) return;
    int s = __ldg(src + warp);
    int d = __ldg(dst + warp);
    float4 v = __ldg((const float4*)(x + (size_t)s * HF) + lane);
    float* ag = agg + (size_t)d * HF + lane * 4;
    asm volatile("red.global.add.v4.f32 [%0], {%1, %2, %3, %4};"
                 :: "l"(ag), "f"(v.x), "f"(v.y), "f"(v.z), "f"(v.w)
                 : "memory");
}

// ---------------- cnt -> 1/max(cnt,1), all three arrays in one launch -------
__global__ __launch_bounds__(256) void inv3_kernel(
        float* __restrict__ cA, float* __restrict__ cB,
        float* __restrict__ cH) {
    int i = blockIdx.x * blockDim.x + threadIdx.x;
    if (i < NPAT) {
        cA[i] = 1.0f / fmaxf(cA[i], 1.0f);
        cB[i] = 1.0f / fmaxf(cB[i], 1.0f);
    }
    if (i < NAUT) cH[i] = 1.0f / fmaxf(cH[i], 1.0f);
}

// ---------------- tensor-core fused SAGE GEMM -------------------------------
// C[M,128] = relu( alpha * ( A0*inv0 @ W0^T + A1*inv1 @ W1^T
//                          + A2 @ (W2a + W2b)^T + b0 + b1 ) )
// fp32 emulated via bf16 split: x = hi + lo;  x@w ~= hi@hi + hi@lo + lo@hi.
// mma.sync.m16n8k16.row.col.f32.bf16.bf16.f32; ldmatrix-fed from smem.
#define BM 128
#define BKT 32
#define ASTRIDE 40   // bf16 elems per smem row: 32 data + 8 pad = 80B (16B-mult, LDSM conflict-free)

#define LDSM_X4(r0, r1, r2, r3, addr) \
    asm volatile("ldmatrix.sync.aligned.m8n8.x4.shared.b16 {%0,%1,%2,%3}, [%4];" \
        : "=r"(r0), "=r"(r1), "=r"(r2), "=r"(r3) : "r"(addr))
#define LDSM_X2(r0, r1, addr) \
    asm volatile("ldmatrix.sync.aligned.m8n8.x2.shared.b16 {%0,%1}, [%2];" \
        : "=r"(r0), "=r"(r1) : "r"(addr))
#define MMA16816(d, a, b) \
    asm volatile("mma.sync.aligned.m16n8k16.row.col.f32.bf16.bf16.f32 " \
        "{%0,%1,%2,%3}, {%4,%5,%6,%7}, {%8,%9}, {%0,%1,%2,%3};" \
        : "+f"(d[0]), "+f"(d[1]), "+f"(d[2]), "+f"(d[3]) \
        : "r"(a[0]), "r"(a[1]), "r"(a[2]), "r"(a[3]), "r"(b[0]), "r"(b[1]))

__device__ __forceinline__ void split_store_pair(
        __nv_bfloat16* __restrict__ H, __nv_bfloat16* __restrict__ L,
        int idx, float x, float y) {
    __nv_bfloat16 hx = __float2bfloat16(x);
    __nv_bfloat16 hy = __float2bfloat16(y);
    __nv_bfloat16 lx = __float2bfloat16(x - __bfloat162float(hx));
    __nv_bfloat16 ly = __float2bfloat16(y - __bfloat162float(hy));
    *reinterpret_cast<__nv_bfloat162*>(H + idx) = __halves2bfloat162(hx, hy);
    *reinterpret_cast<__nv_bfloat162*>(L + idx) = __halves2bfloat162(lx, ly);
}

__global__ __launch_bounds__(256) void sage_gemm_tc(
    const float* __restrict__ A0, const float* __restrict__ inv0, const float* __restrict__ W0,
    const float* __restrict__ A1, const float* __restrict__ inv1, const float* __restrict__ W1,
    const float* __restrict__ A2, const float* __restrict__ W2a, const float* __restrict__ W2b,
    const float* __restrict__ b0, const float* __restrict__ b1,
    float alpha, int M, float* __restrict__ C)
{
    __shared__ __align__(16) __nv_bfloat16 Ah[128 * ASTRIDE];
    __shared__ __align__(16) __nv_bfloat16 Al[128 * ASTRIDE];
    __shared__ __align__(16) __nv_bfloat16 Bh[128 * ASTRIDE];
    __shared__ __align__(16) __nv_bfloat16 Bl[128 * ASTRIDE];

    const int tid  = threadIdx.x;
    const int lane = tid & 31;
    const int wid  = tid >> 5;
    const int wm   = wid >> 2;       // 0..1  -> 64 output rows each
    const int wn   = wid & 3;        // 0..3  -> 32 output cols each
    const int bm   = blockIdx.x * BM;

    const int ml = tid >> 1;              // 0..127: row handled in load phase
    const int k0 = (tid & 1) * 16;        // 0 or 16
    const int gm = bm + ml;

    float acc[4][4][4];                   // [m-tile i][n-tile j][frag reg]
#pragma unroll
    for (int i = 0; i < 4; i++)
#pragma unroll
        for (int j = 0; j < 4; j++)
#pragma unroll
            for (int r = 0; r < 4; r++) acc[i][j][r] = 0.f;

    const uint32_t ah_b = (uint32_t)__cvta_generic_to_shared(Ah);
    const uint32_t al_b = (uint32_t)__cvta_generic_to_shared(Al);
    const uint32_t bh_b = (uint32_t)__cvta_generic_to_shared(Bh);
    const uint32_t bl_b = (uint32_t)__cvta_generic_to_shared(Bl);

#pragma unroll 1
    for (int s = 0; s < 3; ++s) {
        const float* A = (s == 0) ? A0 : (s == 1) ? A1 : A2;
        if (A == nullptr) continue;
        const float* Wp = (s == 0) ? W0 : (s == 1) ? W1 : W2a;
        const float* Wq = (s == 2) ? W2b : nullptr;
        const float* invp = (s == 0) ? inv0 : (s == 1) ? inv1 : nullptr;

        float sc = 0.f;
        if (gm < M) sc = invp ? __ldg(invp + gm) : 1.0f;

#pragma unroll 1
        for (int kt = 0; kt < HF; kt += BKT) {
            // ---- load fp32, scale, split to bf16 hi/lo, store to smem ----
#pragma unroll
            for (int j4 = 0; j4 < 4; j4++) {
                int kk = k0 + j4 * 4;
                float4 v = make_float4(0.f, 0.f, 0.f, 0.f);
                if (gm < M) {
                    v = __ldg((const float4*)(A + (size_t)gm * HF + kt + kk));
                    v.x *= sc; v.y *= sc; v.z *= sc; v.w *= sc;
                }
                float4 w = __ldg((const float4*)(Wp + (size_t)ml * HF + kt + kk));
                if (Wq) {
                    float4 w2 = __ldg((const float4*)(Wq + (size_t)ml * HF + kt + kk));
                    w.x += w2.x; w.y += w2.y; w.z += w2.z; w.w += w2.w;
                }
                int base = ml * ASTRIDE + kk;
                split_store_pair(Ah, Al, base,     v.x, v.y);
                split_store_pair(Ah, Al, base + 2, v.z, v.w);
                split_store_pair(Bh, Bl, base,     w.x, w.y);
                split_store_pair(Bh, Bl, base + 2, w.z, w.w);
            }
            __syncthreads();

            // ---- mma over two k16 steps ----
#pragma unroll
            for (int kb = 0; kb < BKT; kb += 16) {
                uint32_t bhf[4][2], blf[4][2];
#pragma unroll
                for (int j = 0; j < 4; j++) {
                    uint32_t off = (uint32_t)(((wn * 32 + j * 8 + (lane & 7)) * ASTRIDE
                                               + kb + (lane & 8)) * 2);
                    LDSM_X2(bhf[j][0], bhf[j][1], bh_b + off);
                    LDSM_X2(blf[j][0], blf[j][1], bl_b + off);
                }
#pragma unroll
                for (int i = 0; i < 4; i++) {
                    uint32_t offa = (uint32_t)(((wm * 64 + i * 16 + (lane & 15)) * ASTRIDE
                                                + kb + ((lane >> 4) << 3)) * 2);
                    uint32_t a_h[4], a_l[4];
                    LDSM_X4(a_h[0], a_h[1], a_h[2], a_h[3], ah_b + offa);
                    LDSM_X4(a_l[0], a_l[1], a_l[2], a_l[3], al_b + offa);
#pragma unroll
                    for (int j = 0; j < 4; j++) {
                        MMA16816(acc[i][j], a_h, bhf[j]);
                        MMA16816(acc[i][j], a_h, blf[j]);
                        MMA16816(acc[i][j], a_l, bhf[j]);
                    }
                }
            }
            __syncthreads();
        }
    }

    // ---- epilogue: bias, alpha, relu ----
    const int qrow = lane >> 2;
    const int qcol = (lane & 3) << 1;
    float bv[4][2];
#pragma unroll
    for (int j = 0; j < 4; j++) {
        int col = wn * 32 + j * 8 + qcol;
        float b0v = b0 ? __ldg(b0 + col) : 0.f;
        float b1v = b0 ? __ldg(b0 + col + 1) : 0.f;
        if (b1) { b0v += __ldg(b1 + col); b1v += __ldg(b1 + col + 1); }
        bv[j][0] = b0v; bv[j][1] = b1v;
    }
#pragma unroll
    for (int i = 0; i < 4; i++) {
        int r0 = bm + wm * 64 + i * 16 + qrow;
        int r1 = r0 + 8;
#pragma unroll
        for (int j = 0; j < 4; j++) {
            int col = wn * 32 + j * 8 + qcol;
            if (r0 < M) {
                float2 o;
                o.x = fmaxf(alpha * (acc[i][j][0] + bv[j][0]), 0.f);
                o.y = fmaxf(alpha * (acc[i][j][1] + bv[j][1]), 0.f);
                *reinterpret_cast<float2*>(C + (size_t)r0 * HF + col) = o;
            }
            if (r1 < M) {
                float2 o;
                o.x = fmaxf(alpha * (acc[i][j][2] + bv[j][0]), 0.f);
                o.y = fmaxf(alpha * (acc[i][j][3] + bv[j][1]), 0.f);
                *reinterpret_cast<float2*>(C + (size_t)r1 * HF + col) = o;
            }
        }
    }
}

// ---------------- final head: out[M,8] = p2 @ linW^T + lin_b ----------------
__global__ __launch_bounds__(256) void head_kernel(
        const float* __restrict__ p2,
        const float* __restrict__ W,   // [8,128]
        const float* __restrict__ b,   // [8]
        float* __restrict__ out, int M) {
    int warp = (blockIdx.x * blockDim.x + threadIdx.x) >> 5;
    int lane = threadIdx.x & 31;
    if (warp >= M) return;
    const float* row = p2 + (size_t)warp * HF;
    float v0 = row[lane], v1 = row[lane + 32], v2 = row[lane + 64], v3 = row[lane + 96];
#pragma unroll
    for (int c = 0; c < 8; c++) {
        const float* w = W + c * HF;
        float p = v0 * __ldg(w + lane) + v1 * __ldg(w + lane + 32)
                + v2 * __ldg(w + lane + 64) + v3 * __ldg(w + lane + 96);
#pragma unroll
        for (int o = 16; o; o >>= 1) p += __shfl_xor_sync(0xffffffffu, p, o);
        if (lane == 0) out[(size_t)warp * 8 + c] = p + __ldg(b + c);
    }
}

// ---------------- host orchestration ----------------------------------------
extern "C" void kernel_launch(void* const* d_in, const int* in_sizes, int n_in,
                              void* d_out, int out_size) {
    const float* x_p   = (const float*)d_in[0];
    const float* x_a   = (const float*)d_in[1];
    const int* cites_s = (const int*)d_in[2];
    const int* cites_d = (const int*)d_in[3];
    const int* ao_s    = (const int*)d_in[4];
    const int* ao_d    = (const int*)d_in[5];
    const int* ha_s    = (const int*)d_in[6];
    const int* ha_d    = (const int*)d_in[7];
    const float* l1c_Wl = (const float*)d_in[8];
    const float* l1c_bl = (const float*)d_in[9];
    const float* l1c_Wr = (const float*)d_in[10];
    const float* l1a_Wl = (const float*)d_in[11];
    const float* l1a_bl = (const float*)d_in[12];
    const float* l1a_Wr = (const float*)d_in[13];
    const float* l1h_Wl = (const float*)d_in[14];
    const float* l1h_bl = (const float*)d_in[15];
    const float* l1h_Wr = (const float*)d_in[16];
    const float* l2c_Wl = (const float*)d_in[17];
    const float* l2c_bl = (const float*)d_in[18];
    const float* l2c_Wr = (const float*)d_in[19];
    const float* l2a_Wl = (const float*)d_in[20];
    const float* l2a_bl = (const float*)d_in[21];
    const float* l2a_Wr = (const float*)d_in[22];
    // l2h_* (indices 23..25) are dead code in the reference
    const float* lin_W  = (const float*)d_in[26];
    const float* lin_b  = (const float*)d_in[27];
    float* out = (float*)d_out;

    const int E = in_sizes[2];

    float *aggA, *aggB, *aggH, *p1, *a1, *p2, *cA, *cB, *cH;
    cudaGetSymbolAddress((void**)&aggA, g_aggA);
    cudaGetSymbolAddress((void**)&aggB, g_aggB);
    cudaGetSymbolAddress((void**)&aggH, g_aggH);
    cudaGetSymbolAddress((void**)&p1, g_p1);
    cudaGetSymbolAddress((void**)&a1, g_a1);
    cudaGetSymbolAddress((void**)&p2, g_p2);
    cudaGetSymbolAddress((void**)&cA, g_cA);
    cudaGetSymbolAddress((void**)&cB, g_cB);
    cudaGetSymbolAddress((void**)&cH, g_cH);

    // zero layer-1 aggregation buffers + counts (graph-capturable memset nodes)
    cudaMemsetAsync(aggA, 0, (size_t)NPAT * HF * sizeof(float));
    cudaMemsetAsync(aggB, 0, (size_t)NPAT * HF * sizeof(float));
    cudaMemsetAsync(aggH, 0, (size_t)NAUT * HF * sizeof(float));
    cudaMemsetAsync(cA, 0, NPAT * sizeof(float));
    cudaMemsetAsync(cB, 0, NPAT * sizeof(float));
    cudaMemsetAsync(cH, 0, NAUT * sizeof(float));

    const int SCAT_B = (E * 32 + 255) / 256;
    const int DEG_B = (E + 255) / 256;
    // layer-1 scatters (feature sum) + degree counts.
    scatter_kernel<<<SCAT_B, 256>>>(x_p, cites_s, cites_d, aggA, E);
    scatter_kernel<<<SCAT_B, 256>>>(x_p, ha_s, ha_d, aggH, E);
    scatter_kernel<<<SCAT_B, 256>>>(x_a, ao_s, ao_d, aggB, E);
    degree3_kernel<<<DEG_B, 256>>>(cites_d, ao_d, ha_d, cA, cB, cH, E);

    inv3_kernel<<<(NAUT + 255) / 256, 256>>>(cA, cB, cH);

    const int GP = (NPAT + BM - 1) / BM;   // 391
    const int GA = (NAUT + BM - 1) / BM;   // 782

    // p1 = relu(0.5*(meanA@Wlc^T + meanB@Wla^T + x_p@(Wrc+Wra)^T + blc + bla))
    sage_gemm_tc<<<GP, 256>>>(aggA, cA, l1c_Wl,
                              aggB, cB, l1a_Wl,
                              x_p, l1c_Wr, l1a_Wr,
                              l1c_bl, l1a_bl,
                              0.5f, NPAT, p1);
    // a1 = relu(meanH@Wlh^T + x_a@Wrh^T + blh)
    sage_gemm_tc<<<GA, 256>>>(aggH, cH, l1h_Wl,
                              nullptr, nullptr, nullptr,
                              x_a, l1h_Wr, nullptr,
                              l1h_bl, nullptr,
                              1.0f, NAUT, a1);

    // layer-2 aggregations (same edges => same counts; cA/cB already hold inverses)
    cudaMemsetAsync(aggA, 0, (size_t)NPAT * HF * sizeof(float));
    cudaMemsetAsync(aggB, 0, (size_t)NPAT * HF * sizeof(float));
    scatter_kernel<<<SCAT_B, 256>>>(p1, cites_s, cites_d, aggA, E);
    scatter_kernel<<<SCAT_B, 256>>>(a1, ao_s, ao_d, aggB, E);

    // p2 = relu(0.5*(meanA@Wlc2^T + meanB@Wla2^T + p1@(Wrc2+Wra2)^T + blc2 + bla2))
    sage_gemm_tc<<<GP, 256>>>(aggA, cA, l2c_Wl,
                              aggB, cB, l2a_Wl,
                              p1, l2c_Wr, l2a_Wr,
                              l2c_bl, l2a_bl,
                              0.5f, NPAT, p2);

    // out = p2 @ lin_W^T + lin_b
    head_kernel<<<(NPAT * 32 + 255) / 256, 256>>>(p2, lin_W, lin_b, out, NPAT);
}